// round 6
// baseline (speedup 1.0000x reference)
#include <cuda_runtime.h>

#define B_SZ 4096
#define T_SZ 2048

typedef unsigned long long u64;

__device__ int g_counter;
__device__ int g_order[B_SZ];

// ---------------- fused scheduling prologue: counting sort (descending length) ----
__global__ __launch_bounds__(1024)
void sort_kernel(const int* __restrict__ lengths)
{
    __shared__ int hist[2048];
    const int tid = threadIdx.x;

    hist[tid] = 0; hist[tid + 1024] = 0;
    __syncthreads();

    for (int i = tid; i < B_SZ; i += 1024)
        atomicAdd(&hist[T_SZ - lengths[i]], 1);
    __syncthreads();

    const int o0 = hist[tid], o1 = hist[tid + 1024];
    for (int off = 1; off < 2048; off <<= 1) {
        int v0 = hist[tid]        + ((tid        >= off) ? hist[tid - off]        : 0);
        int v1 = hist[tid + 1024] + ((tid + 1024 >= off) ? hist[tid + 1024 - off] : 0);
        __syncthreads();
        hist[tid] = v0; hist[tid + 1024] = v1;
        __syncthreads();
    }
    hist[tid]        -= o0;          // exclusive prefix = start offsets
    hist[tid + 1024] -= o1;
    __syncthreads();

    for (int i = tid; i < B_SZ; i += 1024) {
        int pos = atomicAdd(&hist[T_SZ - lengths[i]], 1);
        g_order[pos] = i;
    }
    if (tid == 0) g_counter = 0;
}

// ---------------- math helpers ---------------------------------------------------
__device__ __forceinline__ float fast_ex2(float x) {
    float r; asm("ex2.approx.f32 %0, %1;" : "=f"(r) : "f"(x)); return r;
}
__device__ __forceinline__ float fast_rcp(float x) {
    float r; asm("rcp.approx.f32 %0, %1;" : "=f"(r) : "f"(x)); return r;
}
__device__ __forceinline__ float sigmoid_(float x) {          // head only
    return fast_rcp(1.0f + fast_ex2(-1.44269504f * x));
}
__device__ __forceinline__ u64 ffma2(u64 a, u64 b, u64 c) {
    u64 d; asm("fma.rn.f32x2 %0, %1, %2, %3;" : "=l"(d) : "l"(a), "l"(b), "l"(c));
    return d;
}
__device__ __forceinline__ u64 mul2(u64 a, u64 b) {
    u64 d; asm("mul.rn.f32x2 %0, %1, %2;" : "=l"(d) : "l"(a), "l"(b));
    return d;
}
__device__ __forceinline__ u64 pack2(float lo, float hi) {
    u64 r; asm("mov.b64 %0, {%1, %2};" : "=l"(r) : "f"(lo), "f"(hi)); return r;
}
__device__ __forceinline__ void unpack2(u64 v, float& lo, float& hi) {
    asm("mov.b64 {%0, %1}, %2;" : "=f"(lo), "=f"(hi) : "l"(v));
}

// ---------------- main persistent kernel: 2 sequences per warp --------------------
__global__ __launch_bounds__(128, 2)
void bilstm_kernel(const float* __restrict__ x,
                   const int* __restrict__ lengths,
                   const float* __restrict__ w_ih,
                   const float* __restrict__ w_hh,
                   const float* __restrict__ b_ih,
                   const float* __restrict__ b_hh,
                   const float* __restrict__ fc_w,
                   const float* __restrict__ fc_b,
                   const float* __restrict__ fc2_w,
                   const float* __restrict__ fc2_b,
                   float* __restrict__ out)
{
    const int lane = threadIdx.x & 31;
    const int wrp  = threadIdx.x >> 5;

    __shared__ __align__(16) float hsh[4][2][2][32];  // [warp][buf][seq][lane]
    __shared__ __align__(16) float xs[4][2][2][32];   // [warp][seq][ring][lane]

    // Fold sigmoid/tanh argument scales into all gate weights:
    //   sigmoid(v) = rcp(1 + ex2(-1.4427 v)),  tanh(v) = 2 rcp(1 + ex2(-2.8854 v)) - 1
    const float gsc[4] = {-1.44269504f, -1.44269504f, -2.88539008f, -1.44269504f};

    u64 whh[4][16];
    u64 wib[4];                        // (sc * w_ih_row, sc * (b_ih + b_hh))
#pragma unroll
    for (int g = 0; g < 4; ++g) {
        const int row = g * 32 + lane;
        const float sc = gsc[g];
        wib[g] = pack2(sc * __ldg(w_ih + row),
                       sc * (__ldg(b_ih + row) + __ldg(b_hh + row)));
#pragma unroll
        for (int p = 0; p < 16; ++p) {
            float2 wv = *reinterpret_cast<const float2*>(w_hh + row * 32 + 2 * p);
            whh[g][p] = pack2(sc * wv.x, sc * wv.y);
        }
    }

    const unsigned FULL = 0xffffffffu;

    float hA, ccA, hB, ccB;

    // gates -> new (h, c)
    auto update = [&](float gi, float gf, float gg, float go, float& h, float& cc) {
        const float iv = fast_rcp(1.0f + fast_ex2(gi));
        const float fv = fast_rcp(1.0f + fast_ex2(gf));
        const float gv = fmaf(2.0f, fast_rcp(1.0f + fast_ex2(gg)), -1.0f);
        const float ov = fast_rcp(1.0f + fast_ex2(go));
        cc = fmaf(fv, cc, iv * gv);
        const float tv = fmaf(2.0f,
            fast_rcp(1.0f + fast_ex2(-2.88539008f * cc)), -1.0f);
        h = ov * tv;
    };

    // single-sequence matvec -> pre-scaled gate args
    auto matvec = [&](const float* hbase, u64 xt2,
                      float& gi, float& gf, float& gg, float& go) {
        const ulonglong2* hp = reinterpret_cast<const ulonglong2*>(hbase);
        ulonglong2 hv = hp[0];
        u64 a0 = mul2(hv.x, whh[0][0]);
        u64 a1 = mul2(hv.x, whh[1][0]);
        u64 a2 = mul2(hv.x, whh[2][0]);
        u64 a3 = mul2(hv.x, whh[3][0]);
        a0 = ffma2(hv.y, whh[0][1], a0);
        a1 = ffma2(hv.y, whh[1][1], a1);
        a2 = ffma2(hv.y, whh[2][1], a2);
        a3 = ffma2(hv.y, whh[3][1], a3);
#pragma unroll
        for (int q = 1; q < 8; ++q) {
            hv = hp[q];
            a0 = ffma2(hv.x, whh[0][2 * q], a0);
            a1 = ffma2(hv.x, whh[1][2 * q], a1);
            a2 = ffma2(hv.x, whh[2][2 * q], a2);
            a3 = ffma2(hv.x, whh[3][2 * q], a3);
            a0 = ffma2(hv.y, whh[0][2 * q + 1], a0);
            a1 = ffma2(hv.y, whh[1][2 * q + 1], a1);
            a2 = ffma2(hv.y, whh[2][2 * q + 1], a2);
            a3 = ffma2(hv.y, whh[3][2 * q + 1], a3);
        }
        a0 = ffma2(xt2, wib[0], a0);
        a1 = ffma2(xt2, wib[1], a1);
        a2 = ffma2(xt2, wib[2], a2);
        a3 = ffma2(xt2, wib[3], a3);
        float lo, hi;
        unpack2(a0, lo, hi); gi = lo + hi;
        unpack2(a1, lo, hi); gf = lo + hi;
        unpack2(a2, lo, hi); gg = lo + hi;
        unpack2(a3, lo, hi); go = lo + hi;
    };

    // dual-sequence interleaved matvec (independent chains, shared weights)
    auto matvec2 = [&](const float* baseA, const float* baseB, u64 xA, u64 xB,
                       float& giA, float& gfA, float& ggA, float& goA,
                       float& giB, float& gfB, float& ggB, float& goB) {
        const ulonglong2* hpA = reinterpret_cast<const ulonglong2*>(baseA);
        const ulonglong2* hpB = reinterpret_cast<const ulonglong2*>(baseB);
        ulonglong2 va = hpA[0], vb = hpB[0];
        u64 a0 = mul2(va.x, whh[0][0]);  u64 b0 = mul2(vb.x, whh[0][0]);
        u64 a1 = mul2(va.x, whh[1][0]);  u64 b1 = mul2(vb.x, whh[1][0]);
        u64 a2 = mul2(va.x, whh[2][0]);  u64 b2 = mul2(vb.x, whh[2][0]);
        u64 a3 = mul2(va.x, whh[3][0]);  u64 b3 = mul2(vb.x, whh[3][0]);
        a0 = ffma2(va.y, whh[0][1], a0); b0 = ffma2(vb.y, whh[0][1], b0);
        a1 = ffma2(va.y, whh[1][1], a1); b1 = ffma2(vb.y, whh[1][1], b1);
        a2 = ffma2(va.y, whh[2][1], a2); b2 = ffma2(vb.y, whh[2][1], b2);
        a3 = ffma2(va.y, whh[3][1], a3); b3 = ffma2(vb.y, whh[3][1], b3);
#pragma unroll
        for (int q = 1; q < 8; ++q) {
            va = hpA[q]; vb = hpB[q];
            a0 = ffma2(va.x, whh[0][2 * q], a0); b0 = ffma2(vb.x, whh[0][2 * q], b0);
            a1 = ffma2(va.x, whh[1][2 * q], a1); b1 = ffma2(vb.x, whh[1][2 * q], b1);
            a2 = ffma2(va.x, whh[2][2 * q], a2); b2 = ffma2(vb.x, whh[2][2 * q], b2);
            a3 = ffma2(va.x, whh[3][2 * q], a3); b3 = ffma2(vb.x, whh[3][2 * q], b3);
            a0 = ffma2(va.y, whh[0][2 * q + 1], a0); b0 = ffma2(vb.y, whh[0][2 * q + 1], b0);
            a1 = ffma2(va.y, whh[1][2 * q + 1], a1); b1 = ffma2(vb.y, whh[1][2 * q + 1], b1);
            a2 = ffma2(va.y, whh[2][2 * q + 1], a2); b2 = ffma2(vb.y, whh[2][2 * q + 1], b2);
            a3 = ffma2(va.y, whh[3][2 * q + 1], a3); b3 = ffma2(vb.y, whh[3][2 * q + 1], b3);
        }
        a0 = ffma2(xA, wib[0], a0);  b0 = ffma2(xB, wib[0], b0);
        a1 = ffma2(xA, wib[1], a1);  b1 = ffma2(xB, wib[1], b1);
        a2 = ffma2(xA, wib[2], a2);  b2 = ffma2(xB, wib[2], b2);
        a3 = ffma2(xA, wib[3], a3);  b3 = ffma2(xB, wib[3], b3);
        float lo, hi;
        unpack2(a0, lo, hi); giA = lo + hi;  unpack2(b0, lo, hi); giB = lo + hi;
        unpack2(a1, lo, hi); gfA = lo + hi;  unpack2(b1, lo, hi); gfB = lo + hi;
        unpack2(a2, lo, hi); ggA = lo + hi;  unpack2(b2, lo, hi); ggB = lo + hi;
        unpack2(a3, lo, hi); goA = lo + hi;  unpack2(b3, lo, hi); goB = lo + hi;
    };

    // one step for a single sequence
    auto step1 = [&](int seq, float& h, float& cc, int pb, int rb, int i) {
        hsh[wrp][pb][seq][lane] = h;
        __syncwarp();
        float gi, gf, gg, go;
        matvec(&hsh[wrp][pb][seq][0], pack2(xs[wrp][seq][rb][i], 1.0f),
               gi, gf, gg, go);
        update(gi, gf, gg, go, h, cc);
    };

    // one joint step for both sequences (one syncwarp)
    auto step2 = [&](int pbA, int rbA, int pbB, int rbB, int i) {
        hsh[wrp][pbA][0][lane] = hA;
        hsh[wrp][pbB][1][lane] = hB;
        __syncwarp();
        float giA, gfA, ggA, goA, giB, gfB, ggB, goB;
        matvec2(&hsh[wrp][pbA][0][0], &hsh[wrp][pbB][1][0],
                pack2(xs[wrp][0][rbA][i], 1.0f), pack2(xs[wrp][1][rbB][i], 1.0f),
                giA, gfA, ggA, goA, giB, gfB, ggB, goB);
        update(giA, gfA, ggA, goA, hA, ccA);
        update(giB, gfB, ggB, goB, hB, ccB);
    };

    // FC head: sigmoid(fc2(elu(fc1(h))))
    auto head = [&](int seq, float h, int oidx) {
        __syncwarp();
        hsh[wrp][0][seq][lane] = h;
        __syncwarp();
        float o1 = __ldg(fc_b + lane);
        float o2 = __ldg(fc_b + lane + 32);
#pragma unroll
        for (int k = 0; k < 32; ++k) {
            const float hk = hsh[wrp][0][seq][k];
            o1 = fmaf(hk, __ldg(fc_w + lane * 32 + k), o1);
            o2 = fmaf(hk, __ldg(fc_w + (lane + 32) * 32 + k), o2);
        }
        o1 = (o1 > 0.0f) ? o1 : (fast_ex2(1.44269504f * o1) - 1.0f);   // ELU
        o2 = (o2 > 0.0f) ? o2 : (fast_ex2(1.44269504f * o2) - 1.0f);
        float part = o1 * __ldg(fc2_w + lane) + o2 * __ldg(fc2_w + lane + 32);
#pragma unroll
        for (int d = 16; d >= 1; d >>= 1)
            part += __shfl_xor_sync(FULL, part, d);
        if (lane == 0)
            out[oidx] = sigmoid_(part + __ldg(fc2_b));
        __syncwarp();
    };

    for (;;) {
        int s0 = 0;
        if (lane == 0) s0 = atomicAdd(&g_counter, 2);
        s0 = __shfl_sync(FULL, s0, 0);
        if (s0 >= B_SZ) break;

        const int idxA = g_order[s0];
        const int idxB = g_order[s0 + 1];           // B_SZ even: always valid
        const int lenA = __ldg(lengths + idxA);
        const int lenB = __ldg(lengths + idxB);
        const float* xbA = x + (size_t)idxA * T_SZ;
        const float* xbB = x + (size_t)idxB * T_SZ;

        hA = 0.0f; ccA = 0.0f; hB = 0.0f; ccB = 0.0f;

        const int tA = lenA - 1, tB = lenB - 1;
        const int c0A = tA >> 5, c0B = tB >> 5;

        // stage first chunks; prefetch second
        xs[wrp][0][c0A & 1][lane] = __ldg(xbA + (c0A << 5) + lane);
        xs[wrp][1][c0B & 1][lane] = __ldg(xbB + (c0B << 5) + lane);
        float pendA = (c0A > 0) ? __ldg(xbA + ((c0A - 1) << 5) + lane) : 0.0f;
        float pendB = (c0B > 0) ? __ldg(xbB + ((c0B - 1) << 5) + lane) : 0.0f;

        int pbA = 0, pbB = 0;

        // peel each sequence to a 32-step chunk boundary (single mode)
#pragma unroll 1
        for (int i = tA & 31; i >= 0; --i) { step1(0, hA, ccA, pbA, c0A & 1, i); pbA ^= 1; }
#pragma unroll 1
        for (int i = tB & 31; i >= 0; --i) { step1(1, hB, ccB, pbB, c0B & 1, i); pbB ^= 1; }

        int cAi = c0A - 1, cBi = c0B - 1;           // next chunk index per seq
        const int jmin = (c0A < c0B) ? c0A : c0B;   // joint full chunks

#pragma unroll 1
        for (int j = 0; j < jmin; ++j) {
            xs[wrp][0][cAi & 1][lane] = pendA;
            pendA = (cAi > 0) ? __ldg(xbA + ((cAi - 1) << 5) + lane) : 0.0f;
            xs[wrp][1][cBi & 1][lane] = pendB;
            pendB = (cBi > 0) ? __ldg(xbB + ((cBi - 1) << 5) + lane) : 0.0f;
#pragma unroll 2
            for (int i = 31; i >= 0; --i) {
                step2(pbA, cAi & 1, pbB, cBi & 1, i);
                pbA ^= 1; pbB ^= 1;
            }
            --cAi; --cBi;
        }

        // leftover chunks of the longer sequence (single mode; small w/ sorted pairs)
#pragma unroll 1
        for (; cAi >= 0; --cAi) {
            xs[wrp][0][cAi & 1][lane] = pendA;
            pendA = (cAi > 0) ? __ldg(xbA + ((cAi - 1) << 5) + lane) : 0.0f;
#pragma unroll 2
            for (int i = 31; i >= 0; --i) { step1(0, hA, ccA, pbA, cAi & 1, i); pbA ^= 1; }
        }
#pragma unroll 1
        for (; cBi >= 0; --cBi) {
            xs[wrp][1][cBi & 1][lane] = pendB;
            pendB = (cBi > 0) ? __ldg(xbB + ((cBi - 1) << 5) + lane) : 0.0f;
#pragma unroll 2
            for (int i = 31; i >= 0; --i) { step1(1, hB, ccB, pbB, cBi & 1, i); pbB ^= 1; }
        }

        head(0, hA, idxA);
        head(1, hB, idxB);
    }
}

extern "C" void kernel_launch(void* const* d_in, const int* in_sizes, int n_in,
                              void* d_out, int out_size)
{
    const float* x       = (const float*)d_in[0];
    const int*   lengths = (const int*)  d_in[1];
    const float* w_ih    = (const float*)d_in[2];
    const float* w_hh    = (const float*)d_in[3];
    const float* b_ih    = (const float*)d_in[4];
    const float* b_hh    = (const float*)d_in[5];
    const float* fc_w    = (const float*)d_in[6];
    const float* fc_b    = (const float*)d_in[7];
    const float* fc2_w   = (const float*)d_in[8];
    const float* fc2_b   = (const float*)d_in[9];
    float* out = (float*)d_out;

    sort_kernel<<<1, 1024>>>(lengths);
    // 148 SMs x 2 resident blocks (256-reg budget); atomic pair-queue + LPT order.
    bilstm_kernel<<<296, 128>>>(x, lengths, w_ih, w_hh, b_ih, b_hh,
                                fc_w, fc_b, fc2_w, fc2_b, out);
}

// round 7
// speedup vs baseline: 1.1998x; 1.1998x over previous
#include <cuda_runtime.h>

#define B_SZ 4096
#define T_SZ 2048

typedef unsigned long long u64;

__device__ int g_counter;
__device__ int g_order[B_SZ];

// ---------------- fused scheduling prologue: counting sort (descending length) ----
__global__ __launch_bounds__(1024)
void sort_kernel(const int* __restrict__ lengths)
{
    __shared__ int hist[2048];
    const int tid = threadIdx.x;

    hist[tid] = 0; hist[tid + 1024] = 0;
    __syncthreads();

    for (int i = tid; i < B_SZ; i += 1024)
        atomicAdd(&hist[T_SZ - lengths[i]], 1);
    __syncthreads();

    const int o0 = hist[tid], o1 = hist[tid + 1024];
    for (int off = 1; off < 2048; off <<= 1) {
        int v0 = hist[tid]        + ((tid        >= off) ? hist[tid - off]        : 0);
        int v1 = hist[tid + 1024] + ((tid + 1024 >= off) ? hist[tid + 1024 - off] : 0);
        __syncthreads();
        hist[tid] = v0; hist[tid + 1024] = v1;
        __syncthreads();
    }
    hist[tid]        -= o0;          // exclusive prefix = start offsets
    hist[tid + 1024] -= o1;
    __syncthreads();

    for (int i = tid; i < B_SZ; i += 1024) {
        int pos = atomicAdd(&hist[T_SZ - lengths[i]], 1);
        g_order[pos] = i;
    }
    if (tid == 0) g_counter = 0;
}

// ---------------- math helpers ---------------------------------------------------
__device__ __forceinline__ float fast_ex2(float x) {
    float r; asm("ex2.approx.f32 %0, %1;" : "=f"(r) : "f"(x)); return r;
}
__device__ __forceinline__ float fast_rcp(float x) {
    float r; asm("rcp.approx.f32 %0, %1;" : "=f"(r) : "f"(x)); return r;
}
__device__ __forceinline__ float fast_tanh(float x) {
    float r; asm("tanh.approx.f32 %0, %1;" : "=f"(r) : "f"(x)); return r;
}
__device__ __forceinline__ float sigmoid_(float x) {          // head only (exact-ish)
    return fast_rcp(1.0f + fast_ex2(-1.44269504f * x));
}
__device__ __forceinline__ u64 ffma2(u64 a, u64 b, u64 c) {
    u64 d; asm("fma.rn.f32x2 %0, %1, %2, %3;" : "=l"(d) : "l"(a), "l"(b), "l"(c));
    return d;
}
__device__ __forceinline__ u64 add2(u64 a, u64 b) {
    u64 d; asm("add.rn.f32x2 %0, %1, %2;" : "=l"(d) : "l"(a), "l"(b));
    return d;
}
__device__ __forceinline__ u64 pack2(float lo, float hi) {
    u64 r; asm("mov.b64 %0, {%1, %2};" : "=l"(r) : "f"(lo), "f"(hi)); return r;
}
__device__ __forceinline__ void unpack2(u64 v, float& lo, float& hi) {
    asm("mov.b64 {%0, %1}, %2;" : "=f"(lo), "=f"(hi) : "l"(v));
}

// ---------------- main persistent kernel -----------------------------------------
// Gate-pair layout: accumulate (i,f) and (g,o) as f32x2 with h DUPLICATED in smem,
// so no horizontal adds are needed. Sigmoid args pre-scaled by 0.5 (sigma(v) =
// 0.5 + 0.5*tanh(v/2)); tanh args unscaled; all activations via tanh.approx.
__global__ __launch_bounds__(128, 3)
void bilstm_kernel(const float* __restrict__ x,
                   const int* __restrict__ lengths,
                   const float* __restrict__ w_ih,
                   const float* __restrict__ w_hh,
                   const float* __restrict__ b_ih,
                   const float* __restrict__ b_hh,
                   const float* __restrict__ fc_w,
                   const float* __restrict__ fc_b,
                   const float* __restrict__ fc2_w,
                   const float* __restrict__ fc2_b,
                   float* __restrict__ out)
{
    const int lane = threadIdx.x & 31;
    const int wrp  = threadIdx.x >> 5;

    // h broadcast, duplicated per element: hsh[warp][buf][k] = (h_k, h_k)
    __shared__ __align__(16) float2 hsh[4][2][32];
    // x chunks, duplicated: xs[warp][ring][i] = (x, x)
    __shared__ __align__(16) float2 xs[4][2][32];

    // weights as gate pairs: wif[k] = (0.5*W_i[k], 0.5*W_f[k]),
    //                        wgo[k] = (1.0*W_g[k], 0.5*W_o[k])
    u64 wif[32], wgo[32];
    u64 bif, bgo;            // (w_ih pair) handled separately from (bias pair)
    u64 xif, xgo;            // scaled w_ih pairs
    {
        const int ri = lane, rf = 32 + lane, rg = 64 + lane, ro = 96 + lane;
        const float si = 0.5f, sf = 0.5f, sg = 1.0f, so = 0.5f;
#pragma unroll
        for (int k = 0; k < 32; ++k) {
            wif[k] = pack2(si * __ldg(w_hh + ri * 32 + k),
                           sf * __ldg(w_hh + rf * 32 + k));
            wgo[k] = pack2(sg * __ldg(w_hh + rg * 32 + k),
                           so * __ldg(w_hh + ro * 32 + k));
        }
        xif = pack2(si * __ldg(w_ih + ri), sf * __ldg(w_ih + rf));
        xgo = pack2(sg * __ldg(w_ih + rg), so * __ldg(w_ih + ro));
        bif = pack2(si * (__ldg(b_ih + ri) + __ldg(b_hh + ri)),
                    sf * (__ldg(b_ih + rf) + __ldg(b_hh + rf)));
        bgo = pack2(sg * (__ldg(b_ih + rg) + __ldg(b_hh + rg)),
                    so * (__ldg(b_ih + ro) + __ldg(b_hh + ro)));
    }

    const unsigned FULL = 0xffffffffu;

    float h, cc;

    // One LSTM step. cb: x ring buffer, i: index in chunk, pb: h buffer.
    auto lstm_step = [&](int cb, int i, int pb) {
        hsh[wrp][pb][lane] = make_float2(h, h);
        __syncwarp();

        // acc init: bias + x * w_ih  (x duplicated pair from smem)
        const u64 xx = *reinterpret_cast<const u64*>(&xs[wrp][cb][i]);
        u64 aif0 = ffma2(xx, xif, bif);
        u64 ago0 = ffma2(xx, xgo, bgo);
        u64 aif1 = 0, ago1 = 0;      // second accumulator pair (zero-init cheap)

        const ulonglong2* hp = reinterpret_cast<const ulonglong2*>(&hsh[wrp][pb][0]);
#pragma unroll
        for (int q = 0; q < 8; ++q) {            // k = 2q, 2q+1
            const ulonglong2 hv = hp[q];         // ((h,h),(h',h')) LDS.128 broadcast
            aif0 = ffma2(hv.x, wif[2 * q], aif0);
            ago0 = ffma2(hv.x, wgo[2 * q], ago0);
            aif0 = ffma2(hv.y, wif[2 * q + 1], aif0);
            ago0 = ffma2(hv.y, wgo[2 * q + 1], ago0);
        }
#pragma unroll
        for (int q = 8; q < 16; ++q) {
            const ulonglong2 hv = hp[q];
            aif1 = ffma2(hv.x, wif[2 * q], aif1);
            ago1 = ffma2(hv.x, wgo[2 * q], ago1);
            aif1 = ffma2(hv.y, wif[2 * q + 1], aif1);
            ago1 = ffma2(hv.y, wgo[2 * q + 1], ago1);
        }
        const u64 aif = add2(aif0, aif1);
        const u64 ago = add2(ago0, ago1);

        float gi, gf, gg, go;
        unpack2(aif, gi, gf);        // pre-scaled: gi = 0.5*raw_i, gf = 0.5*raw_f
        unpack2(ago, gg, go);        // gg = raw_g, go = 0.5*raw_o

        const float iv = fmaf(0.5f, fast_tanh(gi), 0.5f);   // sigmoid(raw_i)
        const float fv = fmaf(0.5f, fast_tanh(gf), 0.5f);
        const float gv = fast_tanh(gg);
        const float ov = fmaf(0.5f, fast_tanh(go), 0.5f);

        cc = fmaf(fv, cc, iv * gv);
        h = ov * fast_tanh(cc);
    };

    for (;;) {
        int s0 = 0;
        if (lane == 0) s0 = atomicAdd(&g_counter, 1);
        s0 = __shfl_sync(FULL, s0, 0);
        if (s0 >= B_SZ) break;

        const int idx = g_order[s0];
        const int len = __ldg(lengths + idx);
        const float* xb = x + (size_t)idx * T_SZ;

        h = 0.0f; cc = 0.0f;

        int t = len - 1;
        const int c0 = t >> 5;
        // stage first (possibly partial) chunk duplicated; prefetch next
        {
            const float v = __ldg(xb + (c0 << 5) + lane);
            xs[wrp][c0 & 1][lane] = make_float2(v, v);
        }
        float pend = (c0 > 0) ? __ldg(xb + ((c0 - 1) << 5) + lane) : 0.0f;

        int pb = 0;

        // peel: partial first chunk
#pragma unroll 1
        for (int i = t & 31; i >= 0; --i) {
            lstm_step(c0 & 1, i, pb);
            pb ^= 1;
        }

        // full chunks: branch-free steps; 1 STS.64 + 1 LDG per 32 steps
#pragma unroll 1
        for (int c = c0 - 1; c >= 0; --c) {
            xs[wrp][c & 1][lane] = make_float2(pend, pend);
            pend = (c > 0) ? __ldg(xb + ((c - 1) << 5) + lane) : 0.0f;
#pragma unroll 2
            for (int i = 31; i >= 0; --i) {
                lstm_step(c & 1, i, pb);
                pb ^= 1;
            }
        }

        // ---- FC head: sigmoid(fc2(elu(fc1(h)))) ----
        __syncwarp();
        hsh[wrp][0][lane] = make_float2(h, h);
        __syncwarp();

        float o1 = __ldg(fc_b + lane);
        float o2 = __ldg(fc_b + lane + 32);
#pragma unroll
        for (int k = 0; k < 32; ++k) {
            const float hk = hsh[wrp][0][k].x;
            o1 = fmaf(hk, __ldg(fc_w + lane * 32 + k), o1);
            o2 = fmaf(hk, __ldg(fc_w + (lane + 32) * 32 + k), o2);
        }
        o1 = (o1 > 0.0f) ? o1 : (fast_ex2(1.44269504f * o1) - 1.0f);  // ELU
        o2 = (o2 > 0.0f) ? o2 : (fast_ex2(1.44269504f * o2) - 1.0f);

        float part = o1 * __ldg(fc2_w + lane) + o2 * __ldg(fc2_w + lane + 32);
#pragma unroll
        for (int d = 16; d >= 1; d >>= 1)
            part += __shfl_xor_sync(FULL, part, d);

        if (lane == 0)
            out[idx] = sigmoid_(part + __ldg(fc2_b));

        __syncwarp();
    }
}

extern "C" void kernel_launch(void* const* d_in, const int* in_sizes, int n_in,
                              void* d_out, int out_size)
{
    const float* x       = (const float*)d_in[0];
    const int*   lengths = (const int*)  d_in[1];
    const float* w_ih    = (const float*)d_in[2];
    const float* w_hh    = (const float*)d_in[3];
    const float* b_ih    = (const float*)d_in[4];
    const float* b_hh    = (const float*)d_in[5];
    const float* fc_w    = (const float*)d_in[6];
    const float* fc_b    = (const float*)d_in[7];
    const float* fc2_w   = (const float*)d_in[8];
    const float* fc2_b   = (const float*)d_in[9];
    float* out = (float*)d_out;

    sort_kernel<<<1, 1024>>>(lengths);
    // 148 SMs x 3 resident blocks (12 warps/SM); atomic queue + LPT order.
    bilstm_kernel<<<444, 128>>>(x, lengths, w_ih, w_hh, b_ih, b_hh,
                                fc_w, fc_b, fc2_w, fc2_b, out);
}